// round 17
// baseline (speedup 1.0000x reference)
#include <cuda_runtime.h>
#include <math.h>

#define HW    256
#define NWARP 8
#define FULLM 0xffffffffu
#define EPSF  1e-9f
#define MINNORM 1.17549435e-38f

// --- fp32 ops with flush-to-zero, matching XLA:GPU ftz semantics ---
__device__ __forceinline__ float fmul_ftz(float a, float b) {
    float r; asm("mul.rn.ftz.f32 %0,%1,%2;" : "=f"(r) : "f"(a), "f"(b)); return r;
}
__device__ __forceinline__ float ffma_ftz(float a, float b, float c) {
    float r; asm("fma.rn.ftz.f32 %0,%1,%2,%3;" : "=f"(r) : "f"(a), "f"(b), "f"(c)); return r;
}
__device__ __forceinline__ float fadd_ftz(float a, float b) {
    float r; asm("add.rn.ftz.f32 %0,%1,%2;" : "=f"(r) : "f"(a), "f"(b)); return r;
}
__device__ __forceinline__ float frcp_approx(float a) {
    float r; asm("rcp.approx.ftz.f32 %0,%1;" : "=f"(r) : "f"(a)); return r;
}

// One scan step. Support j = lane (cd0) and lane+32 (cd1); live mass only at j<=41,
// so for i<208 (d>=48) the upper clip is an exact identity and is skipped (CLAMP=false).
// num is reduced 4 butterfly levels; half-warp partials stored by lanes 0/16 and the
// final (5th-level-equivalent) add happens in the epilogue -> bit-identical grouping.
template<bool CLAMP, bool PROBE>
__device__ __forceinline__ void scan_step(
    int i, int w, int lane,
    float fj0, float fj1,
    float& cd0, float& cd1, float& alive,
    float2 (*s_sc)[HW], float2 (*s_np)[HW], float (*s_invd)[HW])
{
    float2 sc  = s_sc[w][i];
    float ivd  = s_invd[w][i];
    float s1   = 1.0f - sc.x;                // mult = s2*pzg + s1
    float s2   = sc.x + sc.x - 1.0f;
    float t0   = fmaxf(fj0 - sc.y, 0.0f);
    float t1   = fmaxf(fj1 - sc.y, 0.0f);
    if (CLAMP) {
        float dd = (float)(HW - i);
        t0 = fminf(t0, dd);
        t1 = fminf(t1, dd);
    }
    float pz0 = fmul_ftz(t0, ivd);           // clip(j-csf,0,d)/d
    float pz1 = fmul_ftz(t1, ivd);
    float num = ffma_ftz(cd1, pz1, fmul_ftz(cd0, pz0));   // p_z partial (OLD cd)
    cd0 = fmul_ftz(ffma_ftz(s2, pz0, s1), cd0);           // ftz tail flush like ref
    cd1 = fmul_ftz(ffma_ftz(s2, pz1, s1), cd1);
    float nrm = fadd_ftz(cd0, cd1);
    // nrm: full 5-level butterfly (chain-critical)
    nrm = fadd_ftz(nrm, __shfl_xor_sync(FULLM, nrm, 1));
    nrm = fadd_ftz(nrm, __shfl_xor_sync(FULLM, nrm, 2));
    nrm = fadd_ftz(nrm, __shfl_xor_sync(FULLM, nrm, 4));
    nrm = fadd_ftz(nrm, __shfl_xor_sync(FULLM, nrm, 8));
    nrm = fadd_ftz(nrm, __shfl_xor_sync(FULLM, nrm, 16));
    // num: 4 levels, then store half-warp partials (final add deferred to epilogue)
    num = fadd_ftz(num, __shfl_xor_sync(FULLM, num, 1));
    num = fadd_ftz(num, __shfl_xor_sync(FULLM, num, 2));
    num = fadd_ftz(num, __shfl_xor_sync(FULLM, num, 4));
    num = fadd_ftz(num, __shfl_xor_sync(FULLM, num, 8));
    if ((lane & 15) == 0)
        ((float*)(&s_np[w][i]))[lane >> 4] = num;
    // renorm: approx reciprocal (clip preserved); invn>=1 -> never flushes
    float invn = frcp_approx(fmaxf(nrm, 1e-6f));
    cd0 = fmul_ftz(cd0, invn);
    cd1 = fmul_ftz(cd1, invn);
    if (PROBE)   // pinned probe: >0 iff some surviving entry has j > csf
        alive = fmaxf(fminf(cd0, t0), fminf(cd1, t1));
}

__global__ __launch_bounds__(NWARP*32, 1) void spair_obj_kl_kernel(
    const float* __restrict__ z_pres,
    const float* __restrict__ z_prob,
    float* __restrict__ out)
{
    __shared__ float2 s_sc[NWARP][HW];     // {sample, csf} — loop state
    __shared__ float2 s_np[NWARP][HW];     // num half-warp partials (0 if unreached/pinned)
    __shared__ float  s_invd[NWARP][HW];   // per-warp copy -> no cross-warp sync

    const int tid  = threadIdx.x;
    const int lane = tid & 31;
    const int w    = tid >> 5;
    const int b    = blockIdx.x * NWARP + w;

    #pragma unroll
    for (int i = lane; i < HW; i += 32) {
        s_invd[w][i] = 1.0f / (float)(HW - i);
        s_np[w][i]   = make_float2(0.0f, 0.0f);   // unreached -> num=0 -> exact closed form
    }

    // ---- preamble: stage {sample, csf} only (z_prob handled in epilogue) ----
    {
        const float4* zp4 = (const float4*)(z_pres + (size_t)b * HW);
        float4 a0 = zp4[lane*2], a1 = zp4[lane*2+1];
        float smp[8] = { rintf(a0.x), rintf(a0.y), rintf(a0.z), rintf(a0.w),
                         rintf(a1.x), rintf(a1.y), rintf(a1.z), rintf(a1.w) };
        float tot = 0.f;
        #pragma unroll
        for (int k = 0; k < 8; k++) tot += smp[k];
        float incl = tot;
        #pragma unroll
        for (int off = 1; off < 32; off <<= 1) {
            float o = __shfl_up_sync(FULLM, incl, off);
            if (lane >= off) incl += o;
        }
        float run = incl - tot;   // exclusive prefix (csf BEFORE step lane*8)
        #pragma unroll
        for (int k = 0; k < 8; k++) {
            s_sc[w][lane*8 + k] = make_float2(smp[k], run);
            run += smp[k];
        }
    }
    __syncwarp();

    // ---- initial count distribution cd0[j] ~ (1-p) p^j, normalized, FTZ ----
    // j = lane (cd0) and lane+32 (cd1); entries j>=42 flush to exact 0.
    float e2   = (float)exp(2.0);
    float pf   = 1.0f / (e2 + 1.0f);
    float onem = 1.0f - pf;
    double pw[9];
    pw[0] = (double)pf;
    #pragma unroll
    for (int k = 1; k < 9; k++) pw[k] = pw[k-1] * pw[k-1];

    float cdv[2];
    #pragma unroll
    for (int h = 0; h < 2; h++) {
        int j = lane + 32*h;
        double acc = 1.0;
        int jj = j;
        #pragma unroll
        for (int q = 0; q < 9; q++) { if (jj & 1) acc *= pw[q]; jj >>= 1; }
        float wv = (float)acc * onem;
        if (wv < MINNORM) wv = 0.0f;            // ftz flush
        cdv[h] = wv;
    }
    float wsum = cdv[0] + cdv[1];
    #pragma unroll
    for (int off = 1; off < 32; off <<= 1)
        wsum += __shfl_xor_sync(FULLM, wsum, off);
    float cd0 = cdv[0] / wsum;  if (cd0 < MINNORM) cd0 = 0.0f;
    float cd1 = cdv[1] / wsum;  if (cd1 < MINNORM) cd1 = 0.0f;

    const float fj0 = (float)lane;
    const float fj1 = (float)(lane + 32);

    // ---- serial scan: 4-step packs, deferred pin vote (absorbing state ->
    //      extra pinned-state steps write exact num=0) ----
    int exitf = 0;
    #pragma unroll 1
    for (int i4 = 0; i4 < 52; i4++) {          // i < 208: d >= 48 > max live j -> no clamp
        if (exitf) break;
        float alive = 0.f;
        scan_step<false,false>(i4*4+0, w, lane, fj0, fj1, cd0, cd1, alive, s_sc, s_np, s_invd);
        scan_step<false,false>(i4*4+1, w, lane, fj0, fj1, cd0, cd1, alive, s_sc, s_np, s_invd);
        scan_step<false,false>(i4*4+2, w, lane, fj0, fj1, cd0, cd1, alive, s_sc, s_np, s_invd);
        scan_step<false,true >(i4*4+3, w, lane, fj0, fj1, cd0, cd1, alive, s_sc, s_np, s_invd);
        exitf = !__any_sync(FULLM, alive > 0.0f);
    }
    if (!exitf) {
        #pragma unroll 1
        for (int i4 = 52; i4 < 64; i4++) {     // tail steps need the upper clamp
            if (exitf) break;
            float alive = 0.f;
            scan_step<true,false>(i4*4+0, w, lane, fj0, fj1, cd0, cd1, alive, s_sc, s_np, s_invd);
            scan_step<true,false>(i4*4+1, w, lane, fj0, fj1, cd0, cd1, alive, s_sc, s_np, s_invd);
            scan_step<true,false>(i4*4+2, w, lane, fj0, fj1, cd0, cd1, alive, s_sc, s_np, s_invd);
            scan_step<true,true >(i4*4+3, w, lane, fj0, fj1, cd0, cd1, alive, s_sc, s_np, s_invd);
            exitf = !__any_sync(FULLM, alive > 0.0f);
        }
    }
    __syncwarp();

    // ---- epilogue: all KLs in parallel (8 steps per lane), branch-free.
    //      num = P_low + P_high == 5th butterfly level (bit-identical grouping).
    //      num==0 reproduces the pinned closed form exactly. ----
    const float4* pb4 = (const float4*)(z_prob + (size_t)b * HW);
    float4 p0 = pb4[lane*2], p1 = pb4[lane*2+1];
    float prv[8] = { p0.x, p0.y, p0.z, p0.w, p1.x, p1.y, p1.z, p1.w };
    float kl[8];
    #pragma unroll
    for (int k = 0; k < 8; k++) {
        int i = lane*8 + k;
        float2 np = s_np[w][i];
        float num = fadd_ftz(np.x, np.y);
        float pr  = prv[k];
        float c0  = pr * __logf(pr + EPSF)
                  + (1.0f - pr) * __logf(1.0f - pr + EPSF);
        float lpz  = __logf(num + EPSF);
        float l1pz = __logf(1.0f - num + EPSF);
        kl[k] = c0 - pr * lpz - (1.0f - pr) * l1pz;
    }

    // ---- coalesced float4 store of this warp's row ----
    float* ob = out + (size_t)b * HW;
    ((float4*)ob)[lane*2]   = make_float4(kl[0], kl[1], kl[2], kl[3]);
    ((float4*)ob)[lane*2+1] = make_float4(kl[4], kl[5], kl[6], kl[7]);
}

extern "C" void kernel_launch(void* const* d_in, const int* in_sizes, int n_in,
                              void* d_out, int out_size)
{
    const float* z_pres = (const float*)d_in[0];
    const float* z_prob = (const float*)d_in[1];
    float* out = (float*)d_out;
    int B = in_sizes[0] / HW;            // 1024
    spair_obj_kl_kernel<<<B / NWARP, NWARP*32>>>(z_pres, z_prob, out);
}